// round 12
// baseline (speedup 1.0000x reference)
#include <cuda_runtime.h>

#define DD 8
#define BB 4096
#define VV 1024
#define K_SEL 102
#define THREADS 64
#define NROWS (DD * BB)

__device__ int g_samples[NROWS];

__device__ __forceinline__ unsigned fkey(float f) {
    unsigned b = __float_as_uint(f);
    return (b & 0x80000000u) ? ~b : (b | 0x80000000u);
}
__device__ __forceinline__ float keyf(unsigned k) {
    unsigned b = (k & 0x80000000u) ? (k & 0x7FFFFFFFu) : ~k;
    return __uint_as_float(b);
}

__global__ __launch_bounds__(THREADS)
void decode_kernel(const float* __restrict__ logits,
                   const float* __restrict__ uin,
                   const int* __restrict__ curv,
                   float* __restrict__ out_probs,
                   int write_probs)
{
    const int r    = blockIdx.x;              // r = d*B + b
    const int tid  = threadIdx.x;
    const int lane = tid & 31;
    const int wid  = tid >> 5;                // 2 warps
    const float NEG = __int_as_float(0xff800000);
    const size_t base = (size_t)r * VV;
    const int cur = curv[r];
    const unsigned FULL = 0xffffffffu;
    const int t4 = tid * 4;                   // first owned histogram bin

    __shared__ int sh_hist[4][256];           // one page per radix pass: no resets
    __shared__ int sh_wsum[2];
    __shared__ unsigned sh_sel;
    __shared__ int sh_krem;
    __shared__ int sh_cnt;
    __shared__ unsigned sh_maxbin;
    __shared__ unsigned long long sh_best;
    __shared__ float sh_red[2];
    __shared__ float sh_logZ, sh_invt;

#pragma unroll
    for (int p = 0; p < 4; ++p)
        *(int4*)&sh_hist[p][t4] = make_int4(0, 0, 0, 0);
    if (tid == 0) sh_best = 0ull;

    // ---- load 16 elements (four float4 -> MLP=4); u loaded lazily later ----
    float vals[16];
#pragma unroll
    for (int q = 0; q < 4; ++q) {
        float4 lv = ((const float4*)(logits + base))[tid + 64 * q];
        vals[4 * q + 0] = lv.x; vals[4 * q + 1] = lv.y;
        vals[4 * q + 2] = lv.z; vals[4 * q + 3] = lv.w;
    }
    // element index of vals[4q+j] = 4*tid + 256*q + j
    unsigned keys[16];
#pragma unroll
    for (int q = 0; q < 4; ++q)
#pragma unroll
        for (int j = 0; j < 4; ++j) {
            int idx = 4 * tid + 256 * q + j;
            if (idx < cur || idx == 0) vals[4 * q + j] = NEG;
            keys[4 * q + j] = fkey(vals[4 * q + j]);
        }
    __syncthreads();                          // hist pages zeroed, sh_best init

    // ---- exact k-th threshold: radix select, early exact exit ----
    unsigned prefix = 0u;
    int krem = K_SEL;
#pragma unroll
    for (int pass = 0; pass < 4; ++pass) {
        const int shift = 24 - 8 * pass;
        if (pass == 0) {
#pragma unroll
            for (int j = 0; j < 16; ++j)
                atomicAdd(&sh_hist[0][keys[j] >> 24], 1);
        } else {
            const unsigned pm = 0xFFFFFFFFu << (shift + 8);
#pragma unroll
            for (int j = 0; j < 16; ++j)
                if ((keys[j] & pm) == prefix)
                    atomicAdd(&sh_hist[pass][(keys[j] >> shift) & 0xFFu], 1);
        }
        __syncthreads();
        // each thread owns bins [t4, t4+4)
        int4 cc = *(const int4*)&sh_hist[pass][t4];
        int c[4] = {cc.x, cc.y, cc.z, cc.w};
        int cnt = c[0] + c[1] + c[2] + c[3];
        int x = cnt;                          // warp suffix scan (inclusive)
#pragma unroll
        for (int off = 1; off < 32; off <<= 1) {
            int y = __shfl_down_sync(FULL, x, off);
            if (lane + off < 32) x += y;
        }
        if (lane == 0) sh_wsum[wid] = x;
        __syncthreads();
        int suffix = x + ((wid == 0) ? sh_wsum[1] : 0);   // keys in bins >= t4
        int run = suffix - cnt;               // keys in bins > t4+3
        if (suffix >= krem && run < krem) {   // k-th is in one of my 4 bins
            int rr = run, sel = -1, nk = 0, sc = 0;
#pragma unroll
            for (int k = 3; k >= 0; --k) {
                if (sel < 0 && rr + c[k] >= krem) { sel = t4 + k; nk = krem - rr; sc = c[k]; }
                rr += c[k];
            }
            sh_sel = (unsigned)sel; sh_krem = nk; sh_cnt = sc;
        }
        if (pass == 0 && suffix >= 1 && run < 1) {        // top non-empty bin
            int mx = t4;
#pragma unroll
            for (int k = 3; k >= 0; --k) { if (c[k] > 0) { mx = t4 + k; break; } }
            sh_maxbin = (unsigned)mx;
        }
        __syncthreads();
        prefix |= sh_sel << shift;
        krem    = sh_krem;
        if (sh_cnt == krem) break;            // whole boundary bucket kept: exact
    }
    // kept := key >= prefix  (exact threshold or exact bucket floor)

    // m = bucket ceiling of the top non-empty bin: m >= max, within one
    // exponent of it -> exp(x - m) <= 1, softmax shift-invariant.
    const float m = keyf((sh_maxbin << 24) | 0x00FFFFFFu);

    // ---- e = exp(x-m) for kept (reused for probs); deterministic sum ----
    float e[16];
    float s = 0.f;
#pragma unroll
    for (int j = 0; j < 16; ++j) {
        e[j] = (keys[j] >= prefix) ? __expf(vals[j] - m) : 0.f;
        s += e[j];
    }
#pragma unroll
    for (int off = 16; off >= 1; off >>= 1)
        s += __shfl_down_sync(FULL, s, off);
    if (lane == 0) sh_red[wid] = s;
    __syncthreads();
    if (tid == 0) {
        float t = sh_red[0] + sh_red[1];
        sh_logZ = m + __logf(t);
        sh_invt = __fdividef(1.f, t);
    }
    __syncthreads();
    const float logZ = sh_logZ;
    const float invt = sh_invt;

    // ---- probs (p = e*invt) + Gumbel argmax; u loaded only for kept ----
    if (write_probs) {
#pragma unroll
        for (int q = 0; q < 4; ++q)
            ((float4*)(out_probs + base))[tid + 64 * q] =
                make_float4(e[4 * q + 0] * invt, e[4 * q + 1] * invt,
                            e[4 * q + 2] * invt, e[4 * q + 3] * invt);
    }

    unsigned long long best = 0ull;
#pragma unroll
    for (int q = 0; q < 4; ++q)
#pragma unroll
        for (int j = 0; j < 4; ++j) {
            if (keys[4 * q + j] >= prefix) {
                int idx = 4 * tid + 256 * q + j;
                float u  = __ldg(uin + base + idx);
                float g  = -__logf(-__logf(u + 1e-20f) + 1e-20f);
                float sc = (vals[4 * q + j] - logZ) + g;  // same expr as reference
                unsigned long long k64 =
                    ((unsigned long long)fkey(sc) << 32) |
                    (unsigned long long)(0xFFFFFFFFu - (unsigned)idx);
                if (k64 > best) best = k64;
            }
        }
    if (best) atomicMax(&sh_best, best);
    __syncthreads();
    if (tid == 0)
        g_samples[r] = (int)(0xFFFFFFFFu - (unsigned)(sh_best & 0xFFFFFFFFull));
}

__global__ void tokens_kernel(float* __restrict__ out_tok)
{
    int i = blockIdx.x * blockDim.x + threadIdx.x;   // i in [0, B*D)
    if (i >= BB * DD) return;
    int b = i / DD, d = i % DD;
    int s0 = g_samples[b];
    int sd = g_samples[d * BB + b];
    int val = (d == 0 || s0 == 1) ? sd : 0;          // NOTE_TYPE == 1
    out_tok[i] = (float)val;                         // tokens.T flattened [B,D]
}

extern "C" void kernel_launch(void* const* d_in, const int* in_sizes, int n_in,
                              void* d_out, int out_size)
{
    const float* logits = (const float*)d_in[0];
    const float* uin    = (const float*)d_in[1];
    const int*   curv   = (const int*)d_in[2];
    float* out = (float*)d_out;

    const size_t probsN = (size_t)DD * BB * VV;
    const size_t tokN   = (size_t)BB * DD;

    float* out_tok = nullptr;
    float* out_probs = nullptr;
    if ((size_t)out_size >= probsN + tokN) {        // concat: tokens.T then probs
        out_tok = out; out_probs = out + tokN;
    } else if ((size_t)out_size >= probsN) {        // probs only
        out_probs = out;
    } else {                                        // tokens only
        out_tok = out;
    }

    decode_kernel<<<NROWS, THREADS>>>(logits, uin, curv,
                                      out_probs ? out_probs : out,
                                      out_probs != nullptr ? 1 : 0);
    if (out_tok)
        tokens_kernel<<<(BB * DD + 255) / 256, 256>>>(out_tok);
}

// round 13
// speedup vs baseline: 1.4745x; 1.4745x over previous
#include <cuda_runtime.h>

#define DD 8
#define BB 4096
#define VV 1024
#define K_SEL 102
#define THREADS 128
#define NROWS (DD * BB)

__device__ int g_samples[NROWS];

// monotone key: 2 instr (SHF + LOP3)
__device__ __forceinline__ unsigned fkey(float f) {
    unsigned b = __float_as_uint(f);
    return b ^ (((unsigned)((int)b >> 31)) | 0x80000000u);
}
__device__ __forceinline__ float keyf(unsigned k) {
    unsigned b = (k & 0x80000000u) ? (k & 0x7FFFFFFFu) : ~k;
    return __uint_as_float(b);
}

__global__ void nop_kernel() {}

__global__ __launch_bounds__(THREADS)
void decode_kernel(const float* __restrict__ logits,
                   const float* __restrict__ uin,
                   const int* __restrict__ curv,
                   float* __restrict__ out_probs,
                   int write_probs)
{
    const int r    = blockIdx.x;             // r = d*B + b
    const int tid  = threadIdx.x;
    const int lane = tid & 31;
    const int wid  = tid >> 5;                // 4 warps
    const float NEG = __int_as_float(0xff800000);
    const size_t base = (size_t)r * VV;
    const int cur = curv[r];
    const unsigned FULL = 0xffffffffu;
    const int t2 = tid * 2;

    __shared__ __align__(16) int sh_hist[4][256];  // page per pass: no resets
    __shared__ int sh_wsum[4];
    __shared__ unsigned sh_sel;
    __shared__ int sh_krem;
    __shared__ int sh_cnt;
    __shared__ unsigned sh_maxbin;
    __shared__ unsigned long long sh_best;
    __shared__ float sh_red[4];
    __shared__ float sh_logZ, sh_invt;

#pragma unroll
    for (int p = 0; p < 4; ++p) {
        sh_hist[p][tid] = 0;
        sh_hist[p][tid + 128] = 0;
    }
    if (tid == 0) sh_best = 0ull;

    // ---- load 8 elements (two float4 -> MLP=2); u loaded lazily later ----
    float4 lv0 = ((const float4*)(logits + base))[tid];
    float4 lv1 = ((const float4*)(logits + base))[tid + 128];
    float vals[8] = {lv0.x, lv0.y, lv0.z, lv0.w, lv1.x, lv1.y, lv1.z, lv1.w};
    const int vb0 = tid * 4;                  // idx of vals[0..3]
    const int vb1 = tid * 4 + 512;            // idx of vals[4..7]

    // masking fast-path: only groups overlapping [0,cur) or containing idx 0
    if (vb0 < cur || vb0 == 0) {
#pragma unroll
        for (int j = 0; j < 4; ++j) {
            int idx = vb0 + j;
            if (idx < cur || idx == 0) vals[j] = NEG;
        }
    }
    if (vb1 < cur) {                          // general-cur safety (vb1 >= 512)
#pragma unroll
        for (int j = 0; j < 4; ++j)
            if (vb1 + j < cur) vals[4 + j] = NEG;
    }

    unsigned keys[8];
#pragma unroll
    for (int j = 0; j < 8; ++j) keys[j] = fkey(vals[j]);
    __syncthreads();                          // hist pages zeroed, sh_best init

    // ---- exact k-th threshold: radix select, early exact exit ----
    unsigned prefix = 0u;
    int krem = K_SEL;
#pragma unroll
    for (int pass = 0; pass < 4; ++pass) {
        const int shift = 24 - 8 * pass;
        if (pass == 0) {
#pragma unroll
            for (int j = 0; j < 8; ++j)
                atomicAdd(&sh_hist[0][keys[j] >> 24], 1);
        } else {
            const unsigned pm = 0xFFFFFFFFu << (shift + 8);
#pragma unroll
            for (int j = 0; j < 8; ++j)
                if ((keys[j] & pm) == prefix)
                    atomicAdd(&sh_hist[pass][(keys[j] >> shift) & 0xFFu], 1);
        }
        __syncthreads();
        // each thread owns bins {t2, t2+1}: single LDS.64
        int2 cc = *(const int2*)&sh_hist[pass][t2];
        int c0 = cc.x, c1 = cc.y;
        int cnt = c0 + c1;
        int x = cnt;                          // warp suffix scan (inclusive)
#pragma unroll
        for (int off = 1; off < 32; off <<= 1) {
            int y = __shfl_down_sync(FULL, x, off);
            if (lane + off < 32) x += y;
        }
        if (lane == 0) sh_wsum[wid] = x;
        __syncthreads();
        int tail = 0;
#pragma unroll
        for (int w = 1; w < 4; ++w)
            if (w > wid) tail += sh_wsum[w];
        int suffix = x + tail;                // keys in bins >= t2 (within prefix)
        int above  = suffix - cnt;            // keys in bins > t2+1
        if (suffix >= krem && above < krem) { // k-th is in one of my two bins
            if (above + c1 >= krem) { sh_sel = (unsigned)(t2 + 1); sh_krem = krem - above;      sh_cnt = c1; }
            else                    { sh_sel = (unsigned)t2;       sh_krem = krem - above - c1; sh_cnt = c0; }
        }
        if (pass == 0 && suffix >= 1 && above < 1)
            sh_maxbin = (unsigned)((c1 > 0) ? t2 + 1 : t2);   // top non-empty bin
        __syncthreads();
        prefix |= sh_sel << shift;
        krem    = sh_krem;
        if (sh_cnt == krem) break;            // whole boundary bucket kept: exact
    }
    // kept := key >= prefix  (exact threshold or exact bucket floor)

    // m = bucket ceiling of the top non-empty bin: m >= max, within one
    // exponent of it -> exp(x - m) <= 1, softmax shift-invariant.
    const float m = keyf((sh_maxbin << 24) | 0x00FFFFFFu);

    // ---- e = exp(x-m) for kept (reused for probs); deterministic sum ----
    bool kept[8];
    float e[8];
    float s = 0.f;
#pragma unroll
    for (int j = 0; j < 8; ++j) {
        kept[j] = (keys[j] >= prefix);
        e[j] = kept[j] ? __expf(vals[j] - m) : 0.f;
        s += e[j];
    }
#pragma unroll
    for (int off = 16; off >= 1; off >>= 1)
        s += __shfl_down_sync(FULL, s, off);
    if (lane == 0) sh_red[wid] = s;
    __syncthreads();
    if (tid == 0) {
        float t = sh_red[0] + sh_red[1] + sh_red[2] + sh_red[3];
        sh_logZ = m + __logf(t);
        sh_invt = __fdividef(1.f, t);
    }
    __syncthreads();
    const float logZ = sh_logZ;
    const float invt = sh_invt;

    // ---- probs (p = e*invt) + Gumbel argmax; u loaded only for kept ----
    if (write_probs) {
        ((float4*)(out_probs + base))[tid] =
            make_float4(e[0] * invt, e[1] * invt, e[2] * invt, e[3] * invt);
        ((float4*)(out_probs + base))[tid + 128] =
            make_float4(e[4] * invt, e[5] * invt, e[6] * invt, e[7] * invt);
    }

    unsigned long long best = 0ull;
#pragma unroll
    for (int j = 0; j < 8; ++j) {
        if (kept[j]) {
            int idx = (j < 4) ? (vb0 + j) : (vb1 + j - 4);
            float u  = __ldg(uin + base + idx);
            float a  = __logf(u + 1e-20f);
            float g  = -__logf(-a + 1e-20f);
            float sc = (vals[j] - logZ) + g;   // same expr as reference
            unsigned long long k64 =
                ((unsigned long long)fkey(sc) << 32) |
                (unsigned long long)(0xFFFFFFFFu - (unsigned)idx);
            if (k64 > best) best = k64;
        }
    }
    if (best) atomicMax(&sh_best, best);
    __syncthreads();
    if (tid == 0)
        g_samples[r] = (int)(0xFFFFFFFFu - (unsigned)(sh_best & 0xFFFFFFFFull));
}

__global__ void tokens_kernel(float* __restrict__ out_tok)
{
    int i = blockIdx.x * blockDim.x + threadIdx.x;   // i in [0, B*D)
    if (i >= BB * DD) return;
    int b = i / DD, d = i % DD;
    int s0 = g_samples[b];
    int sd = g_samples[d * BB + b];
    int val = (d == 0 || s0 == 1) ? sd : 0;          // NOTE_TYPE == 1
    out_tok[i] = (float)val;                         // tokens.T flattened [B,D]
}

extern "C" void kernel_launch(void* const* d_in, const int* in_sizes, int n_in,
                              void* d_out, int out_size)
{
    const float* logits = (const float*)d_in[0];
    const float* uin    = (const float*)d_in[1];
    const int*   curv   = (const int*)d_in[2];
    float* out = (float*)d_out;

    const size_t probsN = (size_t)DD * BB * VV;
    const size_t tokN   = (size_t)BB * DD;

    float* out_tok = nullptr;
    float* out_probs = nullptr;
    if ((size_t)out_size >= probsN + tokN) {        // concat: tokens.T then probs
        out_tok = out; out_probs = out + tokN;
    } else if ((size_t)out_size >= probsN) {        // probs only
        out_probs = out;
    } else {                                        // tokens only
        out_tok = out;
    }

    // Launch pattern [nop, decode, nop, tokens]: kernel-launch index 5
    // (ncu -s 5 -c 1) = decode -> decode roofline/SASS become visible.
    nop_kernel<<<1, 1>>>();
    decode_kernel<<<NROWS, THREADS>>>(logits, uin, curv,
                                      out_probs ? out_probs : out,
                                      out_probs != nullptr ? 1 : 0);
    nop_kernel<<<1, 1>>>();
    if (out_tok)
        tokens_kernel<<<(BB * DD + 255) / 256, 256>>>(out_tok);
}